// round 4
// baseline (speedup 1.0000x reference)
#include <cuda_runtime.h>
#include <cuda_bf16.h>
#include <cstdint>

#define HDIM 20
#define TPB 64   // 2 warps: warp0 = role 0, warp1 = role 1, same 32 elements

typedef unsigned long long u64;

union F2u { float2 f; u64 u; };
union F4u { float4 f; u64 u[2]; };

__device__ __forceinline__ u64 pack2(float lo, float hi) {
    F2u t; t.f = make_float2(lo, hi); return t.u;
}
__device__ __forceinline__ float lo2(u64 a) { F2u t; t.u = a; return t.f.x; }
__device__ __forceinline__ float hi2(u64 a) { F2u t; t.u = a; return t.f.y; }

__device__ __forceinline__ u64 fma2(u64 a, u64 b, u64 c) {
    u64 d;
    asm("fma.rn.f32x2 %0, %1, %2, %3;" : "=l"(d) : "l"(a), "l"(b), "l"(c));
    return d;
}
__device__ __forceinline__ u64 mul2(u64 a, u64 b) {
    u64 d;
    asm("mul.rn.f32x2 %0, %1, %2;" : "=l"(d) : "l"(a), "l"(b));
    return d;
}
__device__ __forceinline__ u64 add2(u64 a, u64 b) {
    u64 d;
    asm("add.rn.f32x2 %0, %1, %2;" : "=l"(d) : "l"(a), "l"(b));
    return d;
}
__device__ __forceinline__ float ex2f(float x) {
    float y; asm("ex2.approx.f32 %0, %1;" : "=f"(y) : "f"(x)); return y;
}
__device__ __forceinline__ float rcpf(float x) {
    float y; asm("rcp.approx.f32 %0, %1;" : "=f"(y) : "f"(x)); return y;
}
__device__ __forceinline__ u64 ex2x2(u64 a) { return pack2(ex2f(lo2(a)), ex2f(hi2(a))); }
__device__ __forceinline__ u64 rcp2(u64 a)  { return pack2(rcpf(lo2(a)), rcpf(hi2(a))); }

// pre-scales: sigmoid(v) = rcp(1 + ex2(C1*v)), tanh(v) = 2*rcp(1 + ex2(C2*v)) - 1
#define C1 (-1.4426950408889634f)
#define C2 (-2.8853900817779268f)
#define SIGN2 0x8000000080000000ULL

__global__ __launch_bounds__(TPB, 8)
void gru_decoder_kernel(const float* __restrict__ hidden,
                        const float* __restrict__ w_ih,
                        const float* __restrict__ w_hh,
                        const float* __restrict__ b_ih,
                        const float* __restrict__ b_hh,
                        const float* __restrict__ w_l,
                        const float* __restrict__ b_l,
                        float* __restrict__ out,
                        int B, int step)
{
    // Extended W[i][j]: j<20 -> w_hh[i*20+j], j=20,21 -> w_ih[i*2+(j-20)]
    // WQ[p][jj][12], p = gate pair (rows 2p,2p+1 / 20+2p,21+2p / 40+2p,41+2p),
    // jj = column pair (j0=2jj, j1=2jj+1; jj=10 -> x columns 20,21):
    //   c0..3  = C1*{W[2p][j0],    W[2p][j1],    W[2p+1][j0],  W[2p+1][j1]}   (r)
    //   c4..7  = C1*{W[20+2p][j0], W[20+2p][j1], W[21+2p][j0], W[21+2p][j1]}  (z)
    //   c8..11 = C2*{W[40+2p][j0], W[40+2p][j1], W[41+2p][j0], W[41+2p][j1]}  (n)
    __shared__ __align__(16) float WQ[10][11][12];
    __shared__ __align__(8)  float2 BQP[10][4];  // (r),(z),(n_hh),(n_ih) bias pairs, scaled
    __shared__ __align__(16) float WLY[10][4];   // {wl0_j0, wl0_j1, wl1_j0, wl1_j1}
    __shared__ float BL2[2];
    __shared__ u64 HX[2][TPB][9];                // double-buffered exchange, stride 9 u64

    const int tid = threadIdx.x;

    for (int idx = tid; idx < 10 * 11 * 12; idx += TPB) {
        int p  = idx / 132;
        int r  = idx % 132;
        int jj = r / 12;
        int c  = r % 12;
        int g  = c >> 2;            // 0=r, 1=z, 2=n
        int s  = c & 3;             // bit1 = row offset, bit0 = col offset
        int row = ((g == 0) ? 2*p : (g == 1) ? 20 + 2*p : 40 + 2*p) + (s >> 1);
        int j   = ((jj < 10) ? 2*jj : 20) + (s & 1);
        float w = (j < 20) ? w_hh[row * 20 + j] : w_ih[row * 2 + (j - 20)];
        WQ[p][jj][c] = w * ((g == 2) ? C2 : C1);
    }
    if (tid < 10) {
        int p = tid;
        BQP[p][0] = make_float2(C1 * (b_ih[2*p]      + b_hh[2*p]),
                                C1 * (b_ih[2*p + 1]  + b_hh[2*p + 1]));
        BQP[p][1] = make_float2(C1 * (b_ih[20 + 2*p] + b_hh[20 + 2*p]),
                                C1 * (b_ih[21 + 2*p] + b_hh[21 + 2*p]));
        BQP[p][2] = make_float2(C2 * b_hh[40 + 2*p], C2 * b_hh[41 + 2*p]);
        BQP[p][3] = make_float2(C2 * b_ih[40 + 2*p], C2 * b_ih[41 + 2*p]);
        // y weights for column pair jj=p
        WLY[p][0] = w_l[2*p];
        WLY[p][1] = w_l[2*p + 1];
        WLY[p][2] = w_l[20 + 2*p];
        WLY[p][3] = w_l[21 + 2*p];
    }
    if (tid < 2) BL2[tid] = b_l[tid];
    __syncthreads();

    const int lane = tid & 31;
    const int role = tid >> 5;               // whole-warp uniform
    const int e    = blockIdx.x * 32 + lane; // element (same for both warps)
    if (e >= B) return;

    const int own_off = 5 * role;
    const int oth_off = 5 - own_off;

    // h as natural pairs: hpair[jj] = (h[2jj], h[2jj+1])
    u64 hpair[10];
    {
        const float4* hsrc = (const float4*)(hidden + (size_t)e * HDIM);
#pragma unroll
        for (int q = 0; q < 5; ++q) {
            float4 v = hsrc[q];
            hpair[2*q]     = pack2(v.x, v.y);
            hpair[2*q + 1] = pack2(v.z, v.w);
        }
    }

    const u64 ONE2 = pack2(1.0f, 1.0f);
    const u64 TWO2 = pack2(2.0f, 2.0f);
    const u64 NEG1 = pack2(-1.0f, -1.0f);

    const float yb0 = role ? 0.0f : BL2[0];
    const float yb1 = role ? 0.0f : BL2[1];

    u64 xp = 0;                                  // (x0, x1) pair
    float* outb = out + (size_t)e * step * 2;

    const float*  wqb  = &WQ[own_off][0][0];
    const float2* bqb  = &BQP[own_off][0];
    const float*  wlyb = &WLY[own_off][0];
    u64* myslot = &HX[0][tid][0];
    u64* thslot = &HX[0][tid ^ 32][0];
    const ptrdiff_t bufstride = &HX[1][0][0] - &HX[0][0][0];

#pragma unroll 1
    for (int t = 0; t < step; ++t) {
        const int buf = t & 1;
        u64* ms = myslot + (buf ? bufstride : 0);
        u64* ts = thslot + (buf ? bufstride : 0);

        u64 hn_new[5];

#pragma unroll
        for (int q = 0; q < 5; ++q) {
            const float* wq = wqb + q * 132;

            // jj = 0 peel (mul2 init)
            F4u R, Z, Nw;
            R.f  = *(const float4*)(wq + 0);
            Z.f  = *(const float4*)(wq + 4);
            Nw.f = *(const float4*)(wq + 8);
            u64 Ar0 = mul2(R.u[0],  hpair[0]);
            u64 Ar1 = mul2(R.u[1],  hpair[0]);
            u64 Az0 = mul2(Z.u[0],  hpair[0]);
            u64 Az1 = mul2(Z.u[1],  hpair[0]);
            u64 An0 = mul2(Nw.u[0], hpair[0]);
            u64 An1 = mul2(Nw.u[1], hpair[0]);

#pragma unroll
            for (int jj = 1; jj < 10; ++jj) {
                R.f  = *(const float4*)(wq + jj * 12);
                Z.f  = *(const float4*)(wq + jj * 12 + 4);
                Nw.f = *(const float4*)(wq + jj * 12 + 8);
                const u64 hj = hpair[jj];
                Ar0 = fma2(R.u[0],  hj, Ar0);
                Ar1 = fma2(R.u[1],  hj, Ar1);
                Az0 = fma2(Z.u[0],  hj, Az0);
                Az1 = fma2(Z.u[1],  hj, Az1);
                An0 = fma2(Nw.u[0], hj, An0);
                An1 = fma2(Nw.u[1], hj, An1);
            }

            // x slot (jj = 10): r,z accumulate; n's x part is separate (inn)
            R.f  = *(const float4*)(wq + 120);
            Z.f  = *(const float4*)(wq + 124);
            Nw.f = *(const float4*)(wq + 128);
            Ar0 = fma2(R.u[0], xp, Ar0);
            Ar1 = fma2(R.u[1], xp, Ar1);
            Az0 = fma2(Z.u[0], xp, Az0);
            Az1 = fma2(Z.u[1], xp, Az1);
            u64 In0 = mul2(Nw.u[0], xp);
            u64 In1 = mul2(Nw.u[1], xp);

            // horizontal reduce + bias pairs
            F2u br; br.f = bqb[q * 4 + 0];
            F2u bz; bz.f = bqb[q * 4 + 1];
            F2u bh; bh.f = bqb[q * 4 + 2];
            F2u bi; bi.f = bqb[q * 4 + 3];
            const u64 rArg = add2(pack2(lo2(Ar0) + hi2(Ar0), lo2(Ar1) + hi2(Ar1)), br.u);
            const u64 zArg = add2(pack2(lo2(Az0) + hi2(Az0), lo2(Az1) + hi2(Az1)), bz.u);
            const u64 hnv  = add2(pack2(lo2(An0) + hi2(An0), lo2(An1) + hi2(An1)), bh.u);
            const u64 innv = add2(pack2(lo2(In0) + hi2(In0), lo2(In1) + hi2(In1)), bi.u);

            // gates (args pre-scaled by C1 / C2)
            const u64 rv = rcp2(add2(ex2x2(rArg), ONE2));
            const u64 zv = rcp2(add2(ex2x2(zArg), ONE2));
            const u64 s  = fma2(rv, hnv, innv);
            const u64 nv = fma2(TWO2, rcp2(add2(ex2x2(s), ONE2)), NEG1);

            const u64 hold = hpair[own_off + q];
            const u64 t1 = fma2(zv, hold, nv);            // z*h + n
            hn_new[q] = fma2(zv ^ SIGN2, nv, t1);         // (z*h + n) - z*n
        }

        // partial y over own 10 dims (pair FMAs + horizontal)
        F4u wl; wl.f = *(const float4*)(wlyb);
        u64 Y0 = mul2(wl.u[0], hn_new[0]);
        u64 Y1 = mul2(wl.u[1], hn_new[0]);
#pragma unroll
        for (int q = 1; q < 5; ++q) {
            wl.f = *(const float4*)(wlyb + q * 4);
            Y0 = fma2(wl.u[0], hn_new[q], Y0);
            Y1 = fma2(wl.u[1], hn_new[q], Y1);
        }
        const float y0p = lo2(Y0) + hi2(Y0) + yb0;
        const float y1p = lo2(Y1) + hi2(Y1) + yb1;
        const u64 ypMine = pack2(y0p, y1p);

        // exchange: write own new pairs + y partial, one barrier, read partner
#pragma unroll
        for (int q = 0; q < 5; ++q) ms[q] = hn_new[q];
        ms[5] = ypMine;
        __syncthreads();

        const u64 ypFull = add2(ypMine, ts[5]);
#pragma unroll
        for (int q = 0; q < 5; ++q) {
            hpair[own_off + q] = hn_new[q];
            hpair[oth_off + q] = ts[q];
        }

        // output time-reversed: y_t -> slot (step-1-t); one store per element
        if (!role) {
            F2u yo; yo.u = ypFull;
            *(float2*)(outb + (size_t)(step - 1 - t) * 2) = yo.f;
        }
        xp = ypFull;
    }
}

extern "C" void kernel_launch(void* const* d_in, const int* in_sizes, int n_in,
                              void* d_out, int out_size) {
    const float* hidden = (const float*)d_in[0];
    const float* w_ih   = (const float*)d_in[1];
    const float* w_hh   = (const float*)d_in[2];
    const float* b_ih   = (const float*)d_in[3];
    const float* b_hh   = (const float*)d_in[4];
    const float* w_l    = (const float*)d_in[5];
    const float* b_l    = (const float*)d_in[6];

    const int B = in_sizes[0] / HDIM;        // hidden is (1, B, 20)
    const int step = out_size / (2 * B);     // out is (B, step, 2)

    const int grid = (B + 31) / 32;          // 32 elements per block, 2 warps
    gru_decoder_kernel<<<grid, TPB>>>(hidden, w_ih, w_hh, b_ih, b_hh, w_l, b_l,
                                      (float*)d_out, B, step);
}